// round 3
// baseline (speedup 1.0000x reference)
#include <cuda_runtime.h>
#include <cuda_bf16.h>

// QuantumConv2D analytical collapse:
//   out[b,c,h,w] = cos(theta[9]) * prod_{3x3 patch} cos(x[b,c,h+i,w+j])
//
// Heisenberg-picture derivation:
//   - RY(theta_q), q != 9, commute with Z_9 and cancel.
//   - RY(t9)^dag Z RY(t9) = cos(t9) Z - sin(t9) X
//   - CNOT chain pulls Z_9 back through CNOTs to Z_0...Z_9 ; X_9 invariant.
//   - Product state: <Z_q> = cos(a_q), <X_9> = sin(0) = 0, ancilla factor cos(0)=1.
//
// R3 strategy: 2 outputs per thread (OUT_W=62 is even -> aligned pairs in-row).
//   Per thread: 6x LDG.64 (3 rows x 4 cols), 12x MUFU.COS, shared vertical
//   products (V1*V2 reused by both outputs), 1x STG.64.
//   92256 threads = 361 blocks x 256. Halves warp count + per-output instrs
//   vs R2; all loads issued before any MUFU (MLP=6).

#define IMG_H 64
#define IMG_W 64
#define OUT_H 62
#define OUT_W 62
#define PAIRS_PER_IMG (OUT_H * (OUT_W / 2))      // 62*31 = 1922
#define N_PAIR (48 * PAIRS_PER_IMG)              // 92256

__global__ __launch_bounds__(256)
void qconv3x3_coscos_pair_kernel(const float* __restrict__ x,
                                 const float* __restrict__ theta,
                                 float* __restrict__ out)
{
    const int t = blockIdx.x * 256 + threadIdx.x;
    if (t >= N_PAIR) return;

    const int bc  = t / PAIRS_PER_IMG;
    const int rem = t - bc * PAIRS_PER_IMG;
    const int r   = rem / (OUT_W / 2);
    const int cp  = rem - r * (OUT_W / 2);
    const int c   = cp * 2;                       // even column -> 8B aligned

    const float* p = x + bc * (IMG_H * IMG_W) + r * IMG_W + c;

    // 6 independent 64-bit loads (cols c..c+3 of 3 rows), max MLP first.
    const float2 r0a = *(const float2*)(p);
    const float2 r0b = *(const float2*)(p + 2);
    const float2 r1a = *(const float2*)(p + IMG_W);
    const float2 r1b = *(const float2*)(p + IMG_W + 2);
    const float2 r2a = *(const float2*)(p + 2 * IMG_W);
    const float2 r2b = *(const float2*)(p + 2 * IMG_W + 2);

    // 12 MUFU.COS
    const float c00 = __cosf(r0a.x), c01 = __cosf(r0a.y), c02 = __cosf(r0b.x), c03 = __cosf(r0b.y);
    const float c10 = __cosf(r1a.x), c11 = __cosf(r1a.y), c12 = __cosf(r1b.x), c13 = __cosf(r1b.y);
    const float c20 = __cosf(r2a.x), c21 = __cosf(r2a.y), c22 = __cosf(r2b.x), c23 = __cosf(r2b.y);

    // vertical (column) products
    const float V0 = c00 * c10 * c20;
    const float V1 = c01 * c11 * c21;
    const float V2 = c02 * c12 * c22;
    const float V3 = c03 * c13 * c23;

    const float cT = __cosf(__ldg(&theta[9]));
    const float mc = (V1 * V2) * cT;              // shared middle product

    float2 o;
    o.x = V0 * mc;                                // cols c..c+2
    o.y = V3 * mc;                                // cols c+1..c+3

    // output pair: image offset 15376B (16-div), row 248B, +8c B -> 8B aligned
    *(float2*)(out + bc * (OUT_H * OUT_W) + r * OUT_W + c) = o;
}

extern "C" void kernel_launch(void* const* d_in, const int* in_sizes, int n_in,
                              void* d_out, int out_size)
{
    const float* x     = (const float*)d_in[0];   // [16,3,64,64] float32
    const float* theta = (const float*)d_in[1];   // [10] float32
    float* out = (float*)d_out;                   // [16,3,62,62] float32

    const int blocks = (N_PAIR + 255) / 256;      // 361
    qconv3x3_coscos_pair_kernel<<<blocks, 256>>>(x, theta, out);
}

// round 4
// speedup vs baseline: 1.0385x; 1.0385x over previous
#include <cuda_runtime.h>
#include <cuda_bf16.h>

// QuantumConv2D analytical collapse:
//   out[b,c,h,w] = cos(theta[9]) * prod_{3x3 patch} cos(x[b,c,h+i,w+j])
//
// Heisenberg-picture derivation:
//   - RY(theta_q), q != 9, commute with Z_9 and cancel with daggers.
//   - RY(t9)^dag Z RY(t9) = cos(t9) Z - sin(t9) X
//   - CNOT chain pulls Z_9 back to Z_0...Z_9 ; X_9 invariant.
//   - Product state: <Z_q> = cos(a_q), <X_9> = sin(0) = 0, ancilla factor cos(0)=1.
//
// R4: 1 output/thread (max warp count for latency hiding), zero divisions.
//   grid = (16 row-bands, 48 images), block = 256 = 4 rows x 64 cols.
//   r = tid>>6, c = tid&63 -> pure shift/and index math before the 9 LDGs.
//   9 back-to-back LDG (MLP=9, warp rows are contiguous 128B-line pairs),
//   10 MUFU.COS, balanced product tree, 1 STG.

#define IMG_H 64
#define IMG_W 64
#define OUT_H 62
#define OUT_W 62

__global__ __launch_bounds__(256)
void qconv3x3_coscos_kernel(const float* __restrict__ x,
                            const float* __restrict__ theta,
                            float* __restrict__ out)
{
    const unsigned tid = threadIdx.x;
    const unsigned r   = (blockIdx.x << 2) + (tid >> 6);   // 0..63
    const unsigned c   = tid & 63;                         // 0..63
    if (r >= OUT_H || c >= OUT_W) return;

    const unsigned bc = blockIdx.y;                        // 0..47

    const float* p = x + ((bc << 12) | (r << 6) | c);      // bc*4096 + r*64 + c

    // 9 independent loads first (max MLP), then MUFU, then product tree.
    const float a0 = p[0],            a1 = p[1],             a2 = p[2];
    const float a3 = p[IMG_W],        a4 = p[IMG_W + 1],     a5 = p[IMG_W + 2];
    const float a6 = p[2 * IMG_W],    a7 = p[2 * IMG_W + 1], a8 = p[2 * IMG_W + 2];

    const float c0 = __cosf(a0), c1 = __cosf(a1), c2 = __cosf(a2);
    const float c3 = __cosf(a3), c4 = __cosf(a4), c5 = __cosf(a5);
    const float c6 = __cosf(a6), c7 = __cosf(a7), c8 = __cosf(a8);
    const float cT = __cosf(__ldg(&theta[9]));

    const float p01 = c0 * c1, p23 = c2 * c3, p45 = c4 * c5, p67 = c6 * c7;
    const float prod = ((p01 * p23) * (p45 * p67)) * (c8 * cT);

    out[bc * (OUT_H * OUT_W) + r * OUT_W + c] = prod;
}

extern "C" void kernel_launch(void* const* d_in, const int* in_sizes, int n_in,
                              void* d_out, int out_size)
{
    const float* x     = (const float*)d_in[0];   // [16,3,64,64] float32
    const float* theta = (const float*)d_in[1];   // [10] float32
    float* out = (float*)d_out;                   // [16,3,62,62] float32

    dim3 grid(16, 48);                            // 768 CTAs x 256 threads
    qconv3x3_coscos_kernel<<<grid, 256>>>(x, theta, out);
}